// round 1
// baseline (speedup 1.0000x reference)
#include <cuda_runtime.h>
#include <math.h>

// Problem constants
#define NS 4096
#define NT 4096
#define NVEC (NT/4)          // 1024 float4 per row
#define RBLK 32              // rows per block
#define GY (NS/RBLK)         // 128 row tiles
#define GX 4                 // column tiles (4 * 256 threads * 4 floats = 4096 cols)
#define TPB 256
#define NPDE (GX*GY)         // 512 block partials
#define PB 32                // prep blocks
#define PT 128               // prep threads per block

// Scratch (no allocations allowed anywhere)
static __device__ float4 g_coef[NS];
static __device__ double g_pde[NPDE];
static __device__ double g_bc[PB];
static __device__ double g_tc[PB];

// Faithful port of CubicStretching._solve_depressed_cubic (hyperbolic form)
__device__ __forceinline__ float cubic_root(float Q) {
    const float p  = 6.0f;                       // CHI
    const float sp = 2.4494897427831781f;        // sqrt(6)
    float q = p * Q;                             // CHI * Q
    const float den = 2.0f * p * sp / (3.0f * 1.7320508075688772f); // = 4*sqrt(2)
    float arg = fabsf(q) / den;
    arg = fmaxf(arg, 1.0f);
    float c = 2.0f * sp * coshf(acoshf(arg) / 3.0f);
    return (q >= 0.0f) ? -c : c;
}

// Prep: per-row stencil coefficients + BC loss (row NS-1) + terminal Huber loss (col NT-1)
__global__ void prep_kernel(const float* __restrict__ V) {
    int i = blockIdx.x * PT + threadIdx.x;       // 0..4095

    float C1 = cubic_root(100.0f / 30.0f);       // (B - 0)/ALPHA_STR
    float C2 = cubic_root(-200.0f / 30.0f);      // (B - S_MAX)/ALPHA_STR

    float u   = (float)i * (1.0f / 4095.0f);
    float L   = C2 * u + C1 * (1.0f - u);
    float dL  = C2 - C1;
    float S   = 100.0f + 30.0f * (L * L * L * (1.0f / 6.0f) + L);
    float Su  = 30.0f * dL * (0.5f * L * L + 1.0f);
    float Suu = 30.0f * dL * dL * L;
    float Sn   = S   * (1.0f / 300.0f);
    float Sun  = Su  * (1.0f / 300.0f);
    float Suun = Suu * (1.0f / 300.0f);

    const float INV2DU = 2047.5f;                // 1/(2*DU), DU = 1/4095
    const float INVDU2 = 16769025.0f;            // 1/DU^2 = 4095^2
    float is = 1.0f / Sun;
    float4 c;
    c.x = Sn * Sn;                               // multiplies clipped V_SS
    c.y = INVDU2 * is * is;                      // duu_raw coefficient inside V_SS
    c.z = INV2DU * Suun * is * is * is;          // du_raw coefficient inside V_SS
    c.w = 2.5f * Sn * INV2DU * is;               // ALPHA*S_norm/S_u_n * 1/(2DU) on du_raw
    g_coef[i] = c;

    // BC at S = S_max: row NS-1, all t (t[j] = j/4095)
    float tgt = 1.0f - (100.0f / 300.0f) * expf(-0.05f * (1.0f - u));
    float db  = V[(size_t)(NS - 1) * NT + i] - tgt;
    float bcv = db * db;

    // Terminal condition: col NT-1, softplus payoff on uniform u grid
    float x = 50.0f * (u - (100.0f / 300.0f));
    float payoff = (fmaxf(x, 0.0f) + log1pf(expf(-fabsf(x)))) * 0.02f;
    float dd = V[(size_t)i * NT + (NT - 1)] - payoff;
    float ad = fabsf(dd);
    float tcv = (ad < 0.01f) ? 0.5f * dd * dd : 0.01f * (ad - 0.005f);

    // deterministic block reduce
    #pragma unroll
    for (int o = 16; o; o >>= 1) {
        bcv += __shfl_down_sync(0xffffffffu, bcv, o);
        tcv += __shfl_down_sync(0xffffffffu, tcv, o);
    }
    __shared__ float sb[PT / 32], st[PT / 32];
    int w = threadIdx.x >> 5, l = threadIdx.x & 31;
    if (l == 0) { sb[w] = bcv; st[w] = tcv; }
    __syncthreads();
    if (threadIdx.x == 0) {
        double B = 0.0, T = 0.0;
        #pragma unroll
        for (int k = 0; k < PT / 32; k++) { B += (double)sb[k]; T += (double)st[k]; }
        g_bc[blockIdx.x] = B;
        g_tc[blockIdx.x] = T;
    }
}

// Main PDE residual sum: register sliding window, float4 along t
__global__ void __launch_bounds__(TPB) pde_kernel(const float* __restrict__ V) {
    const float INV2DT = 102375.0f;              // 1/(2*DT_NORM) = 4095/0.04

    int jv = blockIdx.x * TPB + threadIdx.x;     // float4 column index 0..1023
    int j0 = jv << 2;
    int rb = blockIdx.y * RBLK;
    int rlo = (rb == 0) ? 1 : rb;
    int rhi = min(rb + RBLK, NS - 1);            // exclusive; interior rows only

    const float4* __restrict__ Vv = (const float4*)V;
    float4 prev = Vv[(rlo - 1) * NVEC + jv];
    float4 cur  = Vv[rlo * NVEC + jv];
    const bool hasL = (jv != 0);                 // element j0 interior in t?
    const bool hasR = (jv != NVEC - 1);          // element j0+3 interior in t?

    float acc = 0.0f;
    for (int r = rlo; r < rhi; ++r) {
        float4 nxt = Vv[(r + 1) * NVEC + jv];
        float left  = hasL ? V[(size_t)r * NT + j0 - 1] : 0.0f;
        float right = hasR ? V[(size_t)r * NT + j0 + 4] : 0.0f;
        float4 cf = g_coef[r];

        {   // k = 0
            float du  = nxt.x - prev.x;
            float duu = nxt.x - 2.0f * cur.x + prev.x;
            float vss = fminf(fmaxf(duu * cf.y - du * cf.z, -100.0f), 100.0f);
            float vt  = (cur.y - left) * INV2DT;
            float res = vt - cf.x * vss - cf.w * du + 2.5f * cur.x;
            if (hasL) acc = fmaf(res, res, acc);
        }
        {   // k = 1
            float du  = nxt.y - prev.y;
            float duu = nxt.y - 2.0f * cur.y + prev.y;
            float vss = fminf(fmaxf(duu * cf.y - du * cf.z, -100.0f), 100.0f);
            float vt  = (cur.z - cur.x) * INV2DT;
            float res = vt - cf.x * vss - cf.w * du + 2.5f * cur.y;
            acc = fmaf(res, res, acc);
        }
        {   // k = 2
            float du  = nxt.z - prev.z;
            float duu = nxt.z - 2.0f * cur.z + prev.z;
            float vss = fminf(fmaxf(duu * cf.y - du * cf.z, -100.0f), 100.0f);
            float vt  = (cur.w - cur.y) * INV2DT;
            float res = vt - cf.x * vss - cf.w * du + 2.5f * cur.z;
            acc = fmaf(res, res, acc);
        }
        {   // k = 3
            float du  = nxt.w - prev.w;
            float duu = nxt.w - 2.0f * cur.w + prev.w;
            float vss = fminf(fmaxf(duu * cf.y - du * cf.z, -100.0f), 100.0f);
            float vt  = (right - cur.z) * INV2DT;
            float res = vt - cf.x * vss - cf.w * du + 2.5f * cur.w;
            if (hasR) acc = fmaf(res, res, acc);
        }
        prev = cur; cur = nxt;
    }

    // deterministic block reduce -> double partial
    #pragma unroll
    for (int o = 16; o; o >>= 1) acc += __shfl_down_sync(0xffffffffu, acc, o);
    __shared__ float sw[TPB / 32];
    int w = threadIdx.x >> 5, l = threadIdx.x & 31;
    if (l == 0) sw[w] = acc;
    __syncthreads();
    if (threadIdx.x == 0) {
        double s = 0.0;
        #pragma unroll
        for (int k = 0; k < TPB / 32; k++) s += (double)sw[k];
        g_pde[blockIdx.y * GX + blockIdx.x] = s;
    }
}

__global__ void finalize_kernel(float* __restrict__ out) {
    __shared__ double s[256];
    int t = threadIdx.x;

    double v = 0.0;
    for (int k = t; k < NPDE; k += 256) v += g_pde[k];
    s[t] = v; __syncthreads();
    for (int o = 128; o; o >>= 1) { if (t < o) s[t] += s[t + o]; __syncthreads(); }
    double pde = s[0]; __syncthreads();

    s[t] = (t < PB) ? g_bc[t] : 0.0; __syncthreads();
    for (int o = 128; o; o >>= 1) { if (t < o) s[t] += s[t + o]; __syncthreads(); }
    double bc = s[0]; __syncthreads();

    s[t] = (t < PB) ? g_tc[t] : 0.0; __syncthreads();
    for (int o = 128; o; o >>= 1) { if (t < o) s[t] += s[t + o]; __syncthreads(); }

    if (t == 0) {
        double tc = s[0];
        const double n_int = 4094.0 * 4094.0;
        double total = pde / n_int + 10.0 * (bc / 4096.0) + 10.0 * (tc / 4096.0);
        out[0] = (float)total;
    }
}

extern "C" void kernel_launch(void* const* d_in, const int* in_sizes, int n_in,
                              void* d_out, int out_size) {
    const float* V = (const float*)d_in[0];
    float* out = (float*)d_out;
    prep_kernel<<<PB, PT>>>(V);
    dim3 grid(GX, GY);
    pde_kernel<<<grid, TPB>>>(V);
    finalize_kernel<<<1, 256>>>(out);
}

// round 3
// speedup vs baseline: 1.1934x; 1.1934x over previous
#include <cuda_runtime.h>
#include <math.h>

// Problem constants
#define NS 4096
#define NT 4096
#define NVEC (NT/4)          // 1024 float4 per row
#define RBLK 16              // rows per pde block
#define GY (NS/RBLK)         // 256 row tiles
#define GX 4                 // column tiles (4 * 256 threads * 4 floats = 4096 cols)
#define TPB 256
#define NB_PDE (GX*GY)       // 1024 pde blocks
#define NB_BT 8              // boundary/terminal blocks
#define NB_TOTAL (NB_PDE + NB_BT)

// Scratch (no allocations allowed anywhere)
static __device__ double g_pde[NB_PDE];
static __device__ double g_bc[NB_BT];
static __device__ double g_tc[NB_BT];
static __device__ int    g_count = 0;

// Faithful port of CubicStretching._solve_depressed_cubic (hyperbolic form)
__device__ __forceinline__ float cubic_root(float Q) {
    const float p  = 6.0f;                       // CHI
    const float sp = 2.4494897427831781f;        // sqrt(6)
    float q = p * Q;                             // CHI * Q
    const float den = 2.0f * p * sp / (3.0f * 1.7320508075688772f); // = 4*sqrt(2)
    float arg = fabsf(q) / den;
    arg = fmaxf(arg, 1.0f);
    float c = 2.0f * sp * coshf(acoshf(arg) / 3.0f);
    return (q >= 0.0f) ? -c : c;
}

// Per-row stencil coefficients (same math as reference chain rule)
__device__ __forceinline__ float4 row_coef(int i) {
    float C1 = cubic_root(100.0f / 30.0f);       // (B - 0)/ALPHA_STR
    float C2 = cubic_root(-200.0f / 30.0f);      // (B - S_MAX)/ALPHA_STR
    float u   = (float)i * (1.0f / 4095.0f);
    float L   = C2 * u + C1 * (1.0f - u);
    float dL  = C2 - C1;
    float S   = 100.0f + 30.0f * (L * L * L * (1.0f / 6.0f) + L);
    float Su  = 30.0f * dL * (0.5f * L * L + 1.0f);
    float Suu = 30.0f * dL * dL * L;
    float Sn   = S   * (1.0f / 300.0f);
    float Sun  = Su  * (1.0f / 300.0f);
    float Suun = Suu * (1.0f / 300.0f);
    const float INV2DU = 2047.5f;                // 1/(2*DU), DU = 1/4095
    const float INVDU2 = 16769025.0f;            // 1/DU^2 = 4095^2
    float is = 1.0f / Sun;
    float4 c;
    c.x = Sn * Sn;                               // multiplies clipped V_SS
    c.y = INVDU2 * is * is;                      // duu coefficient inside V_SS
    c.z = INV2DU * Suun * is * is * is;          // du coefficient inside V_SS
    c.w = 2.5f * Sn * INV2DU * is;               // ALPHA*S_norm/S_u_n * 1/(2DU)
    return c;
}

__global__ void __launch_bounds__(TPB) fused_kernel(const float* __restrict__ V,
                                                    float* __restrict__ out) {
    __shared__ float4 scoef[RBLK];
    __shared__ double sred[TPB / 32 > 8 ? TPB / 32 : 8];

    const int b   = blockIdx.x;
    const int tid = threadIdx.x;
    const int w   = tid >> 5, l = tid & 31;

    if (b < NB_PDE) {
        // ------------------- PDE residual tile -------------------
        const int gx = b & (GX - 1);
        const int gy = b >> 2;
        const int rb = gy * RBLK;

        if (tid < RBLK) scoef[tid] = row_coef(rb + tid);
        __syncthreads();

        const float INV2DT = 102375.0f;          // 1/(2*DT_NORM) = 4095/0.04
        const int jv = gx * TPB + tid;           // float4 column 0..1023
        const int j0 = jv << 2;
        const bool hasL = (jv != 0);
        const bool hasR = (jv != NVEC - 1);
        // rows of this tile that are interior: [r_begin, r_end)
        const int r_begin = (gy == 0) ? 1 : rb;
        const int r_end   = (gy == GY - 1) ? NS - 1 : rb + RBLK;
        const float4* __restrict__ Vv = (const float4*)V;

        float4 prev = Vv[(size_t)max(rb - 1, 0) * NVEC + jv];
        float4 cur  = Vv[(size_t)rb * NVEC + jv];

        float acc = 0.0f;
        #pragma unroll 4
        for (int rr = 0; rr < RBLK; ++rr) {
            const int r  = rb + rr;
            const int nr = min(r + 1, NS - 1);
            float4 nxt  = Vv[(size_t)nr * NVEC + jv];
            float left  = hasL ? V[(size_t)r * NT + j0 - 1] : 0.0f;
            float right = hasR ? V[(size_t)r * NT + j0 + 4] : 0.0f;
            float4 cf = scoef[rr];

            if (r >= r_begin && r < r_end) {
                {   // k = 0
                    float du  = nxt.x - prev.x;
                    float duu = nxt.x - 2.0f * cur.x + prev.x;
                    float vss = fminf(fmaxf(duu * cf.y - du * cf.z, -100.0f), 100.0f);
                    float vt  = (cur.y - left) * INV2DT;
                    float res = vt - cf.x * vss - cf.w * du + 2.5f * cur.x;
                    if (hasL) acc = fmaf(res, res, acc);
                }
                {   // k = 1
                    float du  = nxt.y - prev.y;
                    float duu = nxt.y - 2.0f * cur.y + prev.y;
                    float vss = fminf(fmaxf(duu * cf.y - du * cf.z, -100.0f), 100.0f);
                    float vt  = (cur.z - cur.x) * INV2DT;
                    float res = vt - cf.x * vss - cf.w * du + 2.5f * cur.y;
                    acc = fmaf(res, res, acc);
                }
                {   // k = 2
                    float du  = nxt.z - prev.z;
                    float duu = nxt.z - 2.0f * cur.z + prev.z;
                    float vss = fminf(fmaxf(duu * cf.y - du * cf.z, -100.0f), 100.0f);
                    float vt  = (cur.w - cur.y) * INV2DT;
                    float res = vt - cf.x * vss - cf.w * du + 2.5f * cur.z;
                    acc = fmaf(res, res, acc);
                }
                {   // k = 3
                    float du  = nxt.w - prev.w;
                    float duu = nxt.w - 2.0f * cur.w + prev.w;
                    float vss = fminf(fmaxf(duu * cf.y - du * cf.z, -100.0f), 100.0f);
                    float vt  = (right - cur.z) * INV2DT;
                    float res = vt - cf.x * vss - cf.w * du + 2.5f * cur.w;
                    if (hasR) acc = fmaf(res, res, acc);
                }
            }
            prev = cur; cur = nxt;
        }

        // deterministic block reduce -> double partial
        #pragma unroll
        for (int o = 16; o; o >>= 1) acc += __shfl_down_sync(0xffffffffu, acc, o);
        __syncthreads();                          // sred reuse barrier vs scoef
        if (l == 0) sred[w] = (double)acc;
        __syncthreads();
        if (tid == 0) {
            double s = 0.0;
            #pragma unroll
            for (int k = 0; k < TPB / 32; k++) s += sred[k];
            g_pde[b] = s;
        }
    } else {
        // ------------------- BC (row NS-1) + terminal (col NT-1) -------------------
        const int kb = b - NB_PDE;                // 0..7
        float bcv = 0.0f, tcv = 0.0f;
        #pragma unroll
        for (int e = 0; e < 2; ++e) {
            int i = kb * 512 + e * 256 + tid;     // 0..4095
            float u = (float)i * (1.0f / 4095.0f);

            // BC at S = S_max (t[j] = j/4095 == u here)
            float tgt = 1.0f - (100.0f / 300.0f) * expf(-0.05f * (1.0f - u));
            float db  = V[(size_t)(NS - 1) * NT + i] - tgt;
            bcv += db * db;

            // Terminal softplus payoff + Huber
            float x = 50.0f * (u - (100.0f / 300.0f));
            float payoff = (fmaxf(x, 0.0f) + log1pf(expf(-fabsf(x)))) * 0.02f;
            float dd = V[(size_t)i * NT + (NT - 1)] - payoff;
            float ad = fabsf(dd);
            tcv += (ad < 0.01f) ? 0.5f * dd * dd : 0.01f * (ad - 0.005f);
        }
        #pragma unroll
        for (int o = 16; o; o >>= 1) {
            bcv += __shfl_down_sync(0xffffffffu, bcv, o);
            tcv += __shfl_down_sync(0xffffffffu, tcv, o);
        }
        __shared__ float sb[TPB / 32], st[TPB / 32];
        if (l == 0) { sb[w] = bcv; st[w] = tcv; }
        __syncthreads();
        if (tid == 0) {
            double B = 0.0, T = 0.0;
            #pragma unroll
            for (int k = 0; k < TPB / 32; k++) { B += (double)sb[k]; T += (double)st[k]; }
            g_bc[kb] = B;
            g_tc[kb] = T;
        }
    }

    // ------------------- last block finalizes -------------------
    __shared__ bool is_last;
    __threadfence();
    if (tid == 0) {
        int prev_cnt = atomicAdd(&g_count, 1);
        is_last = (prev_cnt == NB_TOTAL - 1);
    }
    __syncthreads();
    if (!is_last) return;

    __threadfence();
    volatile double* vpde = g_pde;
    volatile double* vbc  = g_bc;
    volatile double* vtc  = g_tc;

    double v = 0.0;
    for (int k = tid; k < NB_PDE; k += TPB) v += vpde[k];
    double bc = (tid < NB_BT) ? vbc[tid] : 0.0;
    double tc = (tid < NB_BT) ? vtc[tid] : 0.0;

    __shared__ double fp[TPB / 32], fb[TPB / 32], ft[TPB / 32];
    #pragma unroll
    for (int o = 16; o; o >>= 1) {
        v  += __shfl_down_sync(0xffffffffu, v, o);
        bc += __shfl_down_sync(0xffffffffu, bc, o);
        tc += __shfl_down_sync(0xffffffffu, tc, o);
    }
    __syncthreads();
    if (l == 0) { fp[w] = v; fb[w] = bc; ft[w] = tc; }
    __syncthreads();
    if (tid == 0) {
        double P = 0.0, B = 0.0, T = 0.0;
        #pragma unroll
        for (int k = 0; k < TPB / 32; k++) { P += fp[k]; B += fb[k]; T += ft[k]; }
        const double n_int = 4094.0 * 4094.0;
        out[0] = (float)(P / n_int + 10.0 * (B / 4096.0) + 10.0 * (T / 4096.0));
        g_count = 0;                              // self-reset for next graph replay
    }
}

extern "C" void kernel_launch(void* const* d_in, const int* in_sizes, int n_in,
                              void* d_out, int out_size) {
    const float* V = (const float*)d_in[0];
    float* out = (float*)d_out;
    fused_kernel<<<NB_TOTAL, TPB>>>(V, out);
}

// round 5
// speedup vs baseline: 1.4134x; 1.1844x over previous
#include <cuda_runtime.h>
#include <math.h>

// Problem constants
#define NS 4096
#define NT 4096
#define NVEC (NT/4)          // 1024 float4 per row
#define RBLK 16              // rows per pde block
#define GY (NS/RBLK)         // 256 row tiles
#define GX 4                 // column tiles (4 * 256 threads * 4 floats = 4096 cols)
#define TPB 256
#define NB_PDE (GX*GY)       // 1024 pde blocks
#define NB_BT 8              // boundary/terminal blocks
#define NB_TOTAL (NB_PDE + NB_BT)

// Scratch (no allocations allowed anywhere)
static __device__ double g_pde[NB_PDE];
static __device__ double g_bc[NB_BT];
static __device__ double g_tc[NB_BT];
static __device__ int    g_count = 0;

// Faithful port of CubicStretching._solve_depressed_cubic (hyperbolic form)
__device__ __forceinline__ float cubic_root(float Q) {
    const float p  = 6.0f;                       // CHI
    const float sp = 2.4494897427831781f;        // sqrt(6)
    float q = p * Q;                             // CHI * Q
    const float den = 2.0f * p * sp / (3.0f * 1.7320508075688772f); // = 4*sqrt(2)
    float arg = fabsf(q) / den;
    arg = fmaxf(arg, 1.0f);
    float c = 2.0f * sp * coshf(acoshf(arg) / 3.0f);
    return (q >= 0.0f) ? -c : c;
}

// Per-row stencil coefficients (same math as reference chain rule)
__device__ __forceinline__ float4 row_coef(int i) {
    float C1 = cubic_root(100.0f / 30.0f);       // (B - 0)/ALPHA_STR
    float C2 = cubic_root(-200.0f / 30.0f);      // (B - S_MAX)/ALPHA_STR
    float u   = (float)i * (1.0f / 4095.0f);
    float L   = C2 * u + C1 * (1.0f - u);
    float dL  = C2 - C1;
    float S   = 100.0f + 30.0f * (L * L * L * (1.0f / 6.0f) + L);
    float Su  = 30.0f * dL * (0.5f * L * L + 1.0f);
    float Suu = 30.0f * dL * dL * L;
    float Sn   = S   * (1.0f / 300.0f);
    float Sun  = Su  * (1.0f / 300.0f);
    float Suun = Suu * (1.0f / 300.0f);
    const float INV2DU = 2047.5f;                // 1/(2*DU), DU = 1/4095
    const float INVDU2 = 16769025.0f;            // 1/DU^2 = 4095^2
    float is = 1.0f / Sun;
    float4 c;
    c.x = Sn * Sn;                               // multiplies clipped V_SS
    c.y = INVDU2 * is * is;                      // duu coefficient inside V_SS
    c.z = INV2DU * Suun * is * is * is;          // du coefficient inside V_SS
    c.w = 2.5f * Sn * INV2DU * is;               // ALPHA*S_norm/S_u_n * 1/(2DU)
    return c;
}

__global__ void __launch_bounds__(TPB) fused_kernel(const float* __restrict__ V,
                                                    float* __restrict__ out) {
    __shared__ float4 scoef[RBLK];
    __shared__ double sred[TPB / 32 > 8 ? TPB / 32 : 8];

    const int b   = blockIdx.x;
    const int tid = threadIdx.x;
    const int w   = tid >> 5, l = tid & 31;

    if (b < NB_PDE) {
        // ------------------- PDE residual tile -------------------
        const int gx = b & (GX - 1);
        const int gy = b >> 2;
        const int rb = gy * RBLK;

        if (tid < RBLK) scoef[tid] = row_coef(rb + tid);
        __syncthreads();

        const float INV2DT = 102375.0f;          // 1/(2*DT_NORM) = 4095/0.04
        const int jv = gx * TPB + tid;           // float4 column 0..1023
        const int j0 = jv << 2;
        const bool hasL = (jv != 0);
        const bool hasR = (jv != NVEC - 1);
        const float mk0 = hasL ? 1.0f : 0.0f;    // k=0 term included iff j0-1 exists
        const float mk3 = hasR ? 1.0f : 0.0f;    // k=3 term included iff j0+4 exists
        // only warp-edge lanes do scalar halo loads (others get it via shuffle)
        const bool doL = (l == 0)  && hasL;
        const bool doR = (l == 31) && hasR;
        // interior rows of this tile: [rlo, rhi)
        const int rlo = (gy == 0) ? 1 : rb;
        const int rhi = (gy == GY - 1) ? NS - 1 : rb + RBLK;

        const float4* __restrict__ p  = (const float4*)V + (size_t)rlo * NVEC + jv;
        const float*  __restrict__ ps = V + (size_t)rlo * NT + j0;

        float4 prev = p[-NVEC];
        float4 cur  = p[0];

        float acc = 0.0f;
        #pragma unroll 8
        for (int r = rlo; r < rhi; ++r) {
            float4 nxt = p[NVEC];
            p  += NVEC;
            // halos via warp shuffle; warp-edge lanes patch with 1-line loads
            float leftv  = __shfl_up_sync(0xffffffffu,  cur.w, 1);
            float rightv = __shfl_down_sync(0xffffffffu, cur.x, 1);
            if (doL) leftv  = ps[-1];
            if (doR) rightv = ps[4];
            ps += NT;
            float4 cf = scoef[r - rb];

            {   // k = 0
                float du  = nxt.x - prev.x;
                float duu = nxt.x - 2.0f * cur.x + prev.x;
                float vss = fminf(fmaxf(duu * cf.y - du * cf.z, -100.0f), 100.0f);
                float vt  = (cur.y - leftv) * INV2DT;
                float res = vt - cf.x * vss - cf.w * du + 2.5f * cur.x;
                acc = fmaf(res * mk0, res, acc);
            }
            {   // k = 1
                float du  = nxt.y - prev.y;
                float duu = nxt.y - 2.0f * cur.y + prev.y;
                float vss = fminf(fmaxf(duu * cf.y - du * cf.z, -100.0f), 100.0f);
                float vt  = (cur.z - cur.x) * INV2DT;
                float res = vt - cf.x * vss - cf.w * du + 2.5f * cur.y;
                acc = fmaf(res, res, acc);
            }
            {   // k = 2
                float du  = nxt.z - prev.z;
                float duu = nxt.z - 2.0f * cur.z + prev.z;
                float vss = fminf(fmaxf(duu * cf.y - du * cf.z, -100.0f), 100.0f);
                float vt  = (cur.w - cur.y) * INV2DT;
                float res = vt - cf.x * vss - cf.w * du + 2.5f * cur.z;
                acc = fmaf(res, res, acc);
            }
            {   // k = 3
                float du  = nxt.w - prev.w;
                float duu = nxt.w - 2.0f * cur.w + prev.w;
                float vss = fminf(fmaxf(duu * cf.y - du * cf.z, -100.0f), 100.0f);
                float vt  = (rightv - cur.z) * INV2DT;
                float res = vt - cf.x * vss - cf.w * du + 2.5f * cur.w;
                acc = fmaf(res * mk3, res, acc);
            }
            prev = cur; cur = nxt;
        }

        // deterministic block reduce -> double partial
        #pragma unroll
        for (int o = 16; o; o >>= 1) acc += __shfl_down_sync(0xffffffffu, acc, o);
        __syncthreads();                          // sred reuse barrier vs scoef
        if (l == 0) sred[w] = (double)acc;
        __syncthreads();
        if (tid == 0) {
            double s = 0.0;
            #pragma unroll
            for (int k = 0; k < TPB / 32; k++) s += sred[k];
            g_pde[b] = s;
        }
    } else {
        // ------------------- BC (row NS-1) + terminal (col NT-1) -------------------
        const int kb = b - NB_PDE;                // 0..7
        float bcv = 0.0f, tcv = 0.0f;
        #pragma unroll
        for (int e = 0; e < 2; ++e) {
            int i = kb * 512 + e * 256 + tid;     // 0..4095
            float u = (float)i * (1.0f / 4095.0f);

            // BC at S = S_max (t[j] = j/4095 == u here)
            float tgt = 1.0f - (100.0f / 300.0f) * expf(-0.05f * (1.0f - u));
            float db  = V[(size_t)(NS - 1) * NT + i] - tgt;
            bcv += db * db;

            // Terminal softplus payoff + Huber
            float x = 50.0f * (u - (100.0f / 300.0f));
            float payoff = (fmaxf(x, 0.0f) + log1pf(expf(-fabsf(x)))) * 0.02f;
            float dd = V[(size_t)i * NT + (NT - 1)] - payoff;
            float ad = fabsf(dd);
            tcv += (ad < 0.01f) ? 0.5f * dd * dd : 0.01f * (ad - 0.005f);
        }
        #pragma unroll
        for (int o = 16; o; o >>= 1) {
            bcv += __shfl_down_sync(0xffffffffu, bcv, o);
            tcv += __shfl_down_sync(0xffffffffu, tcv, o);
        }
        __shared__ float sb[TPB / 32], st[TPB / 32];
        if (l == 0) { sb[w] = bcv; st[w] = tcv; }
        __syncthreads();
        if (tid == 0) {
            double B = 0.0, T = 0.0;
            #pragma unroll
            for (int k = 0; k < TPB / 32; k++) { B += (double)sb[k]; T += (double)st[k]; }
            g_bc[kb] = B;
            g_tc[kb] = T;
        }
    }

    // ------------------- last block finalizes -------------------
    __shared__ bool is_last;
    __threadfence();
    if (tid == 0) {
        int prev_cnt = atomicAdd(&g_count, 1);
        is_last = (prev_cnt == NB_TOTAL - 1);
    }
    __syncthreads();
    if (!is_last) return;

    __threadfence();
    volatile double* vpde = g_pde;
    volatile double* vbc  = g_bc;
    volatile double* vtc  = g_tc;

    double v = 0.0;
    for (int k = tid; k < NB_PDE; k += TPB) v += vpde[k];
    double bc = (tid < NB_BT) ? vbc[tid] : 0.0;
    double tc = (tid < NB_BT) ? vtc[tid] : 0.0;

    __shared__ double fp[TPB / 32], fb[TPB / 32], ft[TPB / 32];
    #pragma unroll
    for (int o = 16; o; o >>= 1) {
        v  += __shfl_down_sync(0xffffffffu, v, o);
        bc += __shfl_down_sync(0xffffffffu, bc, o);
        tc += __shfl_down_sync(0xffffffffu, tc, o);
    }
    __syncthreads();
    if (l == 0) { fp[w] = v; fb[w] = bc; ft[w] = tc; }
    __syncthreads();
    if (tid == 0) {
        double P = 0.0, B = 0.0, T = 0.0;
        #pragma unroll
        for (int k = 0; k < TPB / 32; k++) { P += fp[k]; B += fb[k]; T += ft[k]; }
        const double n_int = 4094.0 * 4094.0;
        out[0] = (float)(P / n_int + 10.0 * (B / 4096.0) + 10.0 * (T / 4096.0));
        g_count = 0;                              // self-reset for next graph replay
    }
}

extern "C" void kernel_launch(void* const* d_in, const int* in_sizes, int n_in,
                              void* d_out, int out_size) {
    const float* V = (const float*)d_in[0];
    float* out = (float*)d_out;
    fused_kernel<<<NB_TOTAL, TPB>>>(V, out);
}

// round 6
// speedup vs baseline: 1.5427x; 1.0915x over previous
#include <cuda_runtime.h>
#include <math.h>

// Problem constants
#define NS 4096
#define NT 4096
#define NVEC (NT/4)          // 1024 float4 per row
#define RBLK 16              // rows per pde block
#define GY (NS/RBLK)         // 256 row tiles
#define GX 4                 // column tiles (4 * 256 threads * 4 floats = 4096 cols)
#define TPB 256
#define NB_PDE (GX*GY)       // 1024 pde blocks
#define NB_BT 8              // boundary/terminal blocks
#define NB_TOTAL (NB_PDE + NB_BT)   // 1032 <= 148*7 = 1036 -> single wave

// Scratch (no allocations allowed anywhere)
static __device__ double g_pde[NB_PDE];
static __device__ double g_bc[NB_BT];
static __device__ double g_tc[NB_BT];
static __device__ int    g_count = 0;

// Faithful port of CubicStretching._solve_depressed_cubic (hyperbolic form)
__device__ __forceinline__ float cubic_root(float Q) {
    const float p  = 6.0f;                       // CHI
    const float sp = 2.4494897427831781f;        // sqrt(6)
    float q = p * Q;                             // CHI * Q
    const float den = 2.0f * p * sp / (3.0f * 1.7320508075688772f); // = 4*sqrt(2)
    float arg = fabsf(q) / den;
    arg = fmaxf(arg, 1.0f);
    float c = 2.0f * sp * coshf(acoshf(arg) / 3.0f);
    return (q >= 0.0f) ? -c : c;
}

// Per-row stencil coefficients (same math as reference chain rule)
__device__ __forceinline__ float4 row_coef(int i) {
    float C1 = cubic_root(100.0f / 30.0f);       // (B - 0)/ALPHA_STR
    float C2 = cubic_root(-200.0f / 30.0f);      // (B - S_MAX)/ALPHA_STR
    float u   = (float)i * (1.0f / 4095.0f);
    float L   = C2 * u + C1 * (1.0f - u);
    float dL  = C2 - C1;
    float S   = 100.0f + 30.0f * (L * L * L * (1.0f / 6.0f) + L);
    float Su  = 30.0f * dL * (0.5f * L * L + 1.0f);
    float Suu = 30.0f * dL * dL * L;
    float Sn   = S   * (1.0f / 300.0f);
    float Sun  = Su  * (1.0f / 300.0f);
    float Suun = Suu * (1.0f / 300.0f);
    const float INV2DU = 2047.5f;                // 1/(2*DU), DU = 1/4095
    const float INVDU2 = 16769025.0f;            // 1/DU^2 = 4095^2
    float is = 1.0f / Sun;
    float4 c;
    c.x = Sn * Sn;                               // multiplies clipped V_SS
    c.y = INVDU2 * is * is;                      // duu coefficient inside V_SS
    c.z = INV2DU * Suun * is * is * is;          // du coefficient inside V_SS
    c.w = 2.5f * Sn * INV2DU * is;               // ALPHA*S_norm/S_u_n * 1/(2DU)
    return c;
}

__global__ void __launch_bounds__(TPB, 7) fused_kernel(const float* __restrict__ V,
                                                       float* __restrict__ out) {
    __shared__ float4 scoef[RBLK];
    __shared__ double sred[TPB / 32 > 8 ? TPB / 32 : 8];

    const int b   = blockIdx.x;
    const int tid = threadIdx.x;
    const int w   = tid >> 5, l = tid & 31;

    if (b < NB_PDE) {
        // ------------------- PDE residual tile -------------------
        const int gx = b & (GX - 1);
        const int gy = b >> 2;
        const int rb = gy * RBLK;

        if (tid < RBLK) scoef[tid] = row_coef(rb + tid);
        __syncthreads();

        const float INV2DT = 102375.0f;          // 1/(2*DT_NORM) = 4095/0.04
        const int jv = gx * TPB + tid;           // float4 column 0..1023
        const bool hasL = (jv != 0);
        const bool hasR = (jv != NVEC - 1);
        const float mk0 = hasL ? 1.0f : 0.0f;    // k=0 term included iff j0-1 exists
        const float mk3 = hasR ? 1.0f : 0.0f;    // k=3 term included iff j0+4 exists
        // only warp-edge lanes do scalar halo loads (others get it via shuffle)
        const bool doL = (l == 0)  && hasL;
        const bool doR = (l == 31) && hasR;
        // interior rows of this tile: [rlo, rhi)
        const int rlo = (gy == 0) ? 1 : rb;
        const int rhi = (gy == GY - 1) ? NS - 1 : rb + RBLK;

        const float4* __restrict__ p = (const float4*)V + (size_t)rlo * NVEC + jv;

        float4 prev = p[-NVEC];
        float4 cur  = p[0];

        float acc = 0.0f;
        #pragma unroll 8
        for (int r = rlo; r < rhi; ++r) {
            float4 nxt = p[NVEC];
            p += NVEC;                            // p now points to row r+1
            // halos via warp shuffle; warp-edge lanes patch with 1-line loads
            float leftv  = __shfl_up_sync(0xffffffffu,  cur.w, 1);
            float rightv = __shfl_down_sync(0xffffffffu, cur.x, 1);
            // row r scalar addresses as constant offsets from p (row r+1, col j0)
            const float* pf = (const float*)p;
            if (doL) leftv  = pf[-NT - 1];        // V[r*NT + j0 - 1]
            if (doR) rightv = pf[-NT + 4];        // V[r*NT + j0 + 4]
            float4 cf = scoef[r - rb];

            {   // k = 0
                float du  = nxt.x - prev.x;
                float duu = nxt.x - 2.0f * cur.x + prev.x;
                float vss = fminf(fmaxf(duu * cf.y - du * cf.z, -100.0f), 100.0f);
                float vt  = (cur.y - leftv) * INV2DT;
                float res = vt - cf.x * vss - cf.w * du + 2.5f * cur.x;
                acc = fmaf(res * mk0, res, acc);
            }
            {   // k = 1
                float du  = nxt.y - prev.y;
                float duu = nxt.y - 2.0f * cur.y + prev.y;
                float vss = fminf(fmaxf(duu * cf.y - du * cf.z, -100.0f), 100.0f);
                float vt  = (cur.z - cur.x) * INV2DT;
                float res = vt - cf.x * vss - cf.w * du + 2.5f * cur.y;
                acc = fmaf(res, res, acc);
            }
            {   // k = 2
                float du  = nxt.z - prev.z;
                float duu = nxt.z - 2.0f * cur.z + prev.z;
                float vss = fminf(fmaxf(duu * cf.y - du * cf.z, -100.0f), 100.0f);
                float vt  = (cur.w - cur.y) * INV2DT;
                float res = vt - cf.x * vss - cf.w * du + 2.5f * cur.z;
                acc = fmaf(res, res, acc);
            }
            {   // k = 3
                float du  = nxt.w - prev.w;
                float duu = nxt.w - 2.0f * cur.w + prev.w;
                float vss = fminf(fmaxf(duu * cf.y - du * cf.z, -100.0f), 100.0f);
                float vt  = (rightv - cur.z) * INV2DT;
                float res = vt - cf.x * vss - cf.w * du + 2.5f * cur.w;
                acc = fmaf(res * mk3, res, acc);
            }
            prev = cur; cur = nxt;
        }

        // deterministic block reduce -> double partial
        #pragma unroll
        for (int o = 16; o; o >>= 1) acc += __shfl_down_sync(0xffffffffu, acc, o);
        __syncthreads();                          // sred reuse barrier vs scoef
        if (l == 0) sred[w] = (double)acc;
        __syncthreads();
        if (tid == 0) {
            double s = 0.0;
            #pragma unroll
            for (int k = 0; k < TPB / 32; k++) s += sred[k];
            g_pde[b] = s;
        }
    } else {
        // ------------------- BC (row NS-1) + terminal (col NT-1) -------------------
        const int kb = b - NB_PDE;                // 0..7
        float bcv = 0.0f, tcv = 0.0f;
        #pragma unroll
        for (int e = 0; e < 2; ++e) {
            int i = kb * 512 + e * 256 + tid;     // 0..4095
            float u = (float)i * (1.0f / 4095.0f);

            // BC at S = S_max (t[j] = j/4095 == u here)
            float tgt = 1.0f - (100.0f / 300.0f) * expf(-0.05f * (1.0f - u));
            float db  = V[(size_t)(NS - 1) * NT + i] - tgt;
            bcv += db * db;

            // Terminal softplus payoff + Huber
            float x = 50.0f * (u - (100.0f / 300.0f));
            float payoff = (fmaxf(x, 0.0f) + log1pf(expf(-fabsf(x)))) * 0.02f;
            float dd = V[(size_t)i * NT + (NT - 1)] - payoff;
            float ad = fabsf(dd);
            tcv += (ad < 0.01f) ? 0.5f * dd * dd : 0.01f * (ad - 0.005f);
        }
        #pragma unroll
        for (int o = 16; o; o >>= 1) {
            bcv += __shfl_down_sync(0xffffffffu, bcv, o);
            tcv += __shfl_down_sync(0xffffffffu, tcv, o);
        }
        __shared__ float sb[TPB / 32], st[TPB / 32];
        if (l == 0) { sb[w] = bcv; st[w] = tcv; }
        __syncthreads();
        if (tid == 0) {
            double B = 0.0, T = 0.0;
            #pragma unroll
            for (int k = 0; k < TPB / 32; k++) { B += (double)sb[k]; T += (double)st[k]; }
            g_bc[kb] = B;
            g_tc[kb] = T;
        }
    }

    // ------------------- last block finalizes -------------------
    __shared__ bool is_last;
    __threadfence();
    if (tid == 0) {
        int prev_cnt = atomicAdd(&g_count, 1);
        is_last = (prev_cnt == NB_TOTAL - 1);
    }
    __syncthreads();
    if (!is_last) return;

    __threadfence();
    volatile double* vpde = g_pde;
    volatile double* vbc  = g_bc;
    volatile double* vtc  = g_tc;

    double v = 0.0;
    for (int k = tid; k < NB_PDE; k += TPB) v += vpde[k];
    double bc = (tid < NB_BT) ? vbc[tid] : 0.0;
    double tc = (tid < NB_BT) ? vtc[tid] : 0.0;

    __shared__ double fp[TPB / 32], fb[TPB / 32], ft[TPB / 32];
    #pragma unroll
    for (int o = 16; o; o >>= 1) {
        v  += __shfl_down_sync(0xffffffffu, v, o);
        bc += __shfl_down_sync(0xffffffffu, bc, o);
        tc += __shfl_down_sync(0xffffffffu, tc, o);
    }
    __syncthreads();
    if (l == 0) { fp[w] = v; fb[w] = bc; ft[w] = tc; }
    __syncthreads();
    if (tid == 0) {
        double P = 0.0, B = 0.0, T = 0.0;
        #pragma unroll
        for (int k = 0; k < TPB / 32; k++) { P += fp[k]; B += fb[k]; T += ft[k]; }
        const double n_int = 4094.0 * 4094.0;
        out[0] = (float)(P / n_int + 10.0 * (B / 4096.0) + 10.0 * (T / 4096.0));
        g_count = 0;                              // self-reset for next graph replay
    }
}

extern "C" void kernel_launch(void* const* d_in, const int* in_sizes, int n_in,
                              void* d_out, int out_size) {
    const float* V = (const float*)d_in[0];
    float* out = (float*)d_out;
    fused_kernel<<<NB_TOTAL, TPB>>>(V, out);
}